// round 2
// baseline (speedup 1.0000x reference)
#include <cuda_runtime.h>
#include <cuda_bf16.h>
#include <math.h>

// SpikeToCalciumDoubleExp: out[b,t] = sum_{j=0}^{K-1} kernel[j] * u[b, t+K-1-j]
// kernel[j] = (g1^{j+1} - g2^{j+1})/scale  with g = exp(-1/tau), tau1=20, tau2=2.
// Exact truncated-geometric recursion:
//   S(t) = g*S(t-1) + g*u[t+K-1] - g^{K+1}*u[t-1],  out = (S1 - S2)/scale
// Each thread seeds its (P,Q) state with a direct K-tap dot product, then runs
// the recursion for L outputs. ~8 FMA-ops/output instead of 242 -> memory bound.

#define THREADS 256
#define LPT 31                       // outputs per thread
#define CHUNK (THREADS * LPT)        // 7936 outputs per block
#define WIN (CHUNK + 128)            // input window (covers K<=125 tail)
#define SMW (WIN + ((WIN >> 6) << 2))// padded smem size (+4 floats per 64)

__device__ __forceinline__ int padidx(int j) {
    return j + ((j >> 6) << 2);
}

__global__ void __launch_bounds__(THREADS)
spike2calcium_kernel(const float* __restrict__ u, float* __restrict__ out,
                     int K, int T_out, int in_w) {
    __shared__ float  sm[SMW];
    __shared__ float2 wtab[128];

    const int tid = threadIdx.x;
    const int b   = blockIdx.y;
    const int t0  = blockIdx.x * CHUNK;

    // ---- filter constants (compile-time problem parameters) ----
    const float tau1 = 20.0f;   // TAU1 * HZ
    const float tau2 = 2.0f;    // TAU2 * HZ
    const float rr = tau1 / tau2;
    const float dd = tau1 - tau2;
    const float scale = powf(rr, -tau2 / dd) - powf(rr, -tau1 / dd);
    const float inv_scale = 1.0f / scale;
    const float g1 = expf(-1.0f / tau1);
    const float g2 = expf(-1.0f / tau2);

    // weight table: wtab[m-1] = { g1^m/scale, g2^m/scale },  m = 1..K
    if (tid < K) {
        float m = (float)(tid + 1);
        wtab[tid] = make_float2(expf(-m / tau1) * inv_scale,
                                expf(-m / tau2) * inv_scale);
    }

    // ---- cooperative load of input window into padded smem (float4) ----
    const float* row = u + (size_t)b * in_w + t0;
    const int wlen = min(WIN - 4, in_w - t0);   // elements available/needed
    const int nv = wlen >> 2;
    const float4* row4 = (const float4*)row;
    for (int v = tid; v < nv; v += THREADS) {
        float4 val = row4[v];
        int j = v << 2;
        *(float4*)&sm[padidx(j)] = val;         // stays inside one 64-blk, 16B aligned
    }
    for (int j = (nv << 2) + tid; j < wlen; j += THREADS)
        sm[padidx(j)] = row[j];
    __syncthreads();

    // ---- per-thread: seed + recursion ----
    const int base = tid * LPT;                 // local index of first output
    int nout = T_out - t0 - base;
    nout = min(nout, LPT);

    float o[LPT];
    if (nout > 0) {
        // seed: P = sum_m g1^m/scale * u[ts + K - m]  (r = K - m ascending local idx)
        float P = 0.0f, Q = 0.0f;
        #pragma unroll 4
        for (int r = 0; r < K; ++r) {
            float  x = sm[padidx(base + r)];
            float2 w = wtab[K - 1 - r];
            P = fmaf(w.x, x, P);
            Q = fmaf(w.y, x, Q);
        }
        o[0] = P - Q;

        const float cn1 = g1 * inv_scale;
        const float cn2 = g2 * inv_scale;
        const float co1 = powf(g1, (float)(K + 1)) * inv_scale;
        const float co2 = powf(g2, (float)(K + 1)) * inv_scale;  // underflows to 0 for tau2

        #pragma unroll
        for (int t = 1; t < LPT; ++t) {
            float xn = sm[padidx(base + t + K - 1)];
            float xo = sm[padidx(base + t - 1)];
            P = fmaf(g1, P, fmaf(cn1, xn, -co1 * xo));
            Q = fmaf(g2, Q, fmaf(cn2, xn, -co2 * xo));
            o[t] = P - Q;
        }
    }

    // ---- restage outputs through smem for coalesced float4 global stores ----
    __syncthreads();                            // done reading input window
    if (nout > 0) {
        #pragma unroll
        for (int t = 0; t < LPT; ++t)
            if (t < nout) sm[padidx(base + t)] = o[t];
    }
    __syncthreads();

    const int olen = min(CHUNK, T_out - t0);
    float* orow = out + (size_t)b * T_out + t0;
    const int nov = olen >> 2;
    for (int v = tid; v < nov; v += THREADS) {
        int j = v << 2;
        float4 val = *(const float4*)&sm[padidx(j)];
        *(float4*)(orow + j) = val;
    }
    for (int j = (nov << 2) + tid; j < olen; j += THREADS)
        orow[j] = sm[padidx(j)];
}

extern "C" void kernel_launch(void* const* d_in, const int* in_sizes, int n_in,
                              void* d_out, int out_size) {
    const float* u = (const float*)d_in[0];
    const int K = in_sizes[1];                      // 121
    // rows*(T_out+K-1) = in_sizes[0]; rows*T_out = out_size
    const int rows  = (in_sizes[0] - out_size) / (K - 1);   // 1024
    const int T_out = out_size / rows;                      // 30000
    const int in_w  = T_out + K - 1;                        // 30120

    const int n_chunks = (T_out + CHUNK - 1) / CHUNK;       // 4
    dim3 grid(n_chunks, rows);
    spike2calcium_kernel<<<grid, THREADS>>>(u, (float*)d_out, K, T_out, in_w);
}